// round 12
// baseline (speedup 1.0000x reference)
#include <cuda_runtime.h>
#include <math.h>
#include <stdint.h>

// Problem constants (fixed by the reference)
#define HD    128
#define HQ    32
#define HKV   8
#define SEQ   4096
#define BQ    128
#define BKV   128
#define WIN   512
#define CAPV  50.0f
#define EPSV  1e-5f
#define SCL   0.08838834764831845f   // 1/sqrt(128)

#define ROWS_PER_CHUNK 4
#define N_PRE 1

// ---- shared memory layout (32-bit words) ----
#define KS2_OFF   0
#define VS2_OFF   8192
#define QS2_OFF   16384
#define PS2_OFF   16384
#define PARTM_OFF 20480
#define PARTS_OFF 20608
#define SOLD_OFF  20736
#define SCB_OFF   20800
#define SMEM_WORDS 20880

// Work-queue counters. Zero-initialized at module load; the kernel self-resets
// them at the end of every launch (last CTA to finish), so no init launch is
// needed and every graph replay sees counter == 0.
__device__ int g_chunk_counter;
__device__ int g_done_counter;

__device__ __forceinline__ int kv_idx(int kp, int col) {   // stride-128 arrays
    return kp * 128 + (col ^ ((kp & 3) << 3));
}
__device__ __forceinline__ int qp_idx(int kp, int col) {   // stride-64 arrays
    return kp * 64 + (col ^ ((kp & 3) << 3));
}

__device__ __forceinline__ uint32_t pack_bf16x2(float lo, float hi) {
    uint32_t r;
    asm("cvt.rn.bf16x2.f32 %0, %1, %2;" : "=r"(r) : "f"(hi), "f"(lo));
    return r;
}

__device__ __forceinline__ void mma16816(float* c,
    uint32_t a0, uint32_t a1, uint32_t a2, uint32_t a3,
    uint32_t b0, uint32_t b1)
{
    asm volatile(
        "mma.sync.aligned.m16n8k16.row.col.f32.bf16.bf16.f32 "
        "{%0,%1,%2,%3}, {%4,%5,%6,%7}, {%8,%9}, {%0,%1,%2,%3};"
        : "+f"(c[0]), "+f"(c[1]), "+f"(c[2]), "+f"(c[3])
        : "r"(a0), "r"(a1), "r"(a2), "r"(a3), "r"(b0), "r"(b1));
}

struct CopyCtx {
    const float4* src_o;
    float4*       dst_o;
    const float4* src_l;
    float4*       dst_l;
    int row0;
    int nChunkO;
};

// Copy one chunk c. Chunks < nChunkO are 4 full global_o rows (64KB);
// the rest are one (batch,head) lse row each, skipping the updated slice.
__device__ __forceinline__ void copy_chunk(const CopyCtx& cc, int c, int t)
{
    const int SROWS = SEQ - BQ;   // 3968
    if (c < cc.nChunkO) {
        const int vr0 = c * ROWS_PER_CHUNK;
        #pragma unroll
        for (int rr = 0; rr < ROWS_PER_CHUNK; rr += 2) {
            const int vrA = vr0 + rr, vrB = vr0 + rr + 1;
            const int bA = vrA / SROWS, bB = vrB / SROWS;
            const int sA0 = vrA - bA * SROWS, sB0 = vrB - bB * SROWS;
            const int sA = sA0 + (sA0 >= cc.row0 ? BQ : 0);
            const int sB = sB0 + (sB0 >= cc.row0 ? BQ : 0);
            const size_t rbA = (((size_t)bA * SEQ + sA) * HQ * HD) >> 2;
            const size_t rbB = (((size_t)bB * SEQ + sB) * HQ * HD) >> 2;
            float4 tmp[8];
            #pragma unroll
            for (int u = 0; u < 4; u++) tmp[u]     = __ldcs(cc.src_o + rbA + t + u * 256);
            #pragma unroll
            for (int u = 0; u < 4; u++) tmp[4 + u] = __ldcs(cc.src_o + rbB + t + u * 256);
            #pragma unroll
            for (int u = 0; u < 4; u++) __stcs(cc.dst_o + rbA + t + u * 256, tmp[u]);
            #pragma unroll
            for (int u = 0; u < 4; u++) __stcs(cc.dst_o + rbB + t + u * 256, tmp[4 + u]);
        }
    } else {
        const int hb = c - cc.nChunkO;
        const size_t base = (size_t)hb * SEQ;
        const int npos4 = SROWS >> 2;   // 992
        for (int p4 = t; p4 < npos4; p4 += 256) {
            const int p = p4 * 4;
            const int s = p + (p >= cc.row0 ? BQ : 0);
            __stcs(cc.dst_l + ((base + s) >> 2), __ldcs(cc.src_l + ((base + s) >> 2)));
        }
    }
}

__global__ __launch_bounds__(256, 2)
void oswa_fused_kernel(
    const float* __restrict__ q,   const float* __restrict__ k,
    const float* __restrict__ v,   const float* __restrict__ go,
    const float* __restrict__ glse,
    const float* __restrict__ gq,  const float* __restrict__ gk,
    const int* __restrict__ biq,   const int* __restrict__ bikv,
    float* __restrict__ out,
    int B, int nComputeBlocks, int nChunkO, int nChunkTotal)
{
    extern __shared__ uint32_t smw[];
    float* smf = (float*)smw;
    __shared__ int s_chunk2[2];

    const int t    = threadIdx.x;
    const int lane = t & 31;
    const int w    = t >> 5;

    const int bidq  = biq[0];
    const int bidkv = bikv[0];
    const int row0  = bidq * BQ;
    const size_t O_ELEMS = (size_t)B * SEQ * HQ * HD;

    CopyCtx cc;
    cc.src_o = (const float4*)go;
    cc.dst_o = (float4*)out;
    cc.src_l = (const float4*)glse;
    cc.dst_l = (float4*)(out + O_ELEMS);
    cc.row0  = row0;
    cc.nChunkO = nChunkO;

    const int bid = blockIdx.x;

    if (bid < nComputeBlocks) {
        if (bid >= 148) {
            // stagger: second co-resident CTA copies a chunk first
            for (int it = 0; it < N_PRE; it++) {
                if (t == 0) s_chunk2[0] = atomicAdd(&g_chunk_counter, 1);
                __syncthreads();
                const int c = s_chunk2[0];
                __syncthreads();
                if (c < nChunkTotal) copy_chunk(cc, c, t);
                else break;
            }
        }

        // ---------------- attention tile: (batch, head, q-half of 64 rows) ----------------
        const int half  = bid & 1;
        const int h     = (bid >> 1) % HQ;
        const int batch = bid / (2 * HQ);
        const int kh    = h / (HQ / HKV);

        const int r4 = lane & 3;      // row-offset within 4-row group (loaders)
        const int qd = lane >> 2;     // d-group (loaders)

        // ---- K: load + RMSNorm + pack -> Ks2[kpair][j]  (4 rows/warp/iter, 4 iters) ----
        {
            #pragma unroll
            for (int it = 0; it < 4; it++) {
                const int j = it * 32 + w * 4 + r4;
                const float* kr = k + (((size_t)batch * BKV + j) * HKV + kh) * HD;
                float2 xv[8];
                float ss = 0.0f;
                #pragma unroll
                for (int p = 0; p < 8; p++) {
                    xv[p] = *(const float2*)(kr + 2 * qd + 16 * p);
                    ss += xv[p].x * xv[p].x + xv[p].y * xv[p].y;
                }
                ss += __shfl_xor_sync(0xffffffffu, ss, 4);
                ss += __shfl_xor_sync(0xffffffffu, ss, 8);
                ss += __shfl_xor_sync(0xffffffffu, ss, 16);
                const float rstd = rsqrtf(ss * (1.0f / HD) + EPSV);
                #pragma unroll
                for (int p = 0; p < 8; p++) {
                    const float2 g2 = *(const float2*)(gk + kh * HD + 2 * qd + 16 * p);
                    const int kp = qd + 8 * p;
                    smw[KS2_OFF + kv_idx(kp, j)] =
                        pack_bf16x2(xv[p].x * rstd * g2.x, xv[p].y * rstd * g2.y);
                }
            }
        }
        // ---- Q: load + RMSNorm + pack -> Qs2[kpair][i]  (2 iters) ----
        {
            #pragma unroll
            for (int it = 0; it < 2; it++) {
                const int i = it * 32 + w * 4 + r4;
                const int qrow = half * 64 + i;
                const float* qr = q + (((size_t)batch * BQ + qrow) * HQ + h) * HD;
                float2 xv[8];
                float ss = 0.0f;
                #pragma unroll
                for (int p = 0; p < 8; p++) {
                    xv[p] = *(const float2*)(qr + 2 * qd + 16 * p);
                    ss += xv[p].x * xv[p].x + xv[p].y * xv[p].y;
                }
                ss += __shfl_xor_sync(0xffffffffu, ss, 4);
                ss += __shfl_xor_sync(0xffffffffu, ss, 8);
                ss += __shfl_xor_sync(0xffffffffu, ss, 16);
                const float rstd = rsqrtf(ss * (1.0f / HD) + EPSV);
                #pragma unroll
                for (int p = 0; p < 8; p++) {
                    const float2 g2 = *(const float2*)(gq + h * HD + 2 * qd + 16 * p);
                    const int kp = qd + 8 * p;
                    smw[QS2_OFF + qp_idx(kp, i)] =
                        pack_bf16x2(xv[p].x * rstd * g2.x, xv[p].y * rstd * g2.y);
                }
            }
        }
        // ---- V: load + pack pairs along j -> Vs2[jpair][d]  (2 iters) ----
        {
            #pragma unroll
            for (int it = 0; it < 2; it++) {
                const int jp = it * 32 + w * 4 + r4;
                const float* v0 = v + (((size_t)batch * BKV + 2 * jp) * HKV + kh) * HD;
                const float* v1 = v0 + (size_t)HKV * HD;
                #pragma unroll
                for (int p = 0; p < 8; p++) {
                    const int d0 = 2 * qd + 16 * p;
                    const float2 f0 = *(const float2*)(v0 + d0);
                    const float2 f1 = *(const float2*)(v1 + d0);
                    const int idx = VS2_OFF + kv_idx(jp, d0);   // d0 even -> idx,idx+1 contiguous
                    uint2 wv;
                    wv.x = pack_bf16x2(f0.x, f1.x);
                    wv.y = pack_bf16x2(f0.y, f1.y);
                    *(uint2*)(smw + idx) = wv;
                }
            }
        }
        __syncthreads();

        // ---- GEMM1: S[64][128] = Qn * Kn^T via mma.m16n8k16 ----
        const int g   = lane >> 2;     // 0..7
        const int tg  = lane & 3;      // 0..3
        const int wm  = w & 3;
        const int wn  = w >> 2;
        const int m0  = wm * 16;
        const int nbase = wn * 64;

        float acc[8][4];
        #pragma unroll
        for (int nb = 0; nb < 8; nb++)
            #pragma unroll
            for (int c = 0; c < 4; c++) acc[nb][c] = 0.0f;

        #pragma unroll
        for (int ks = 0; ks < 8; ks++) {
            const int kb = ks * 8;
            const uint32_t a0 = smw[QS2_OFF + qp_idx(kb + tg,     m0 + g)];
            const uint32_t a1 = smw[QS2_OFF + qp_idx(kb + tg,     m0 + g + 8)];
            const uint32_t a2 = smw[QS2_OFF + qp_idx(kb + tg + 4, m0 + g)];
            const uint32_t a3 = smw[QS2_OFF + qp_idx(kb + tg + 4, m0 + g + 8)];
            #pragma unroll
            for (int nb = 0; nb < 8; nb++) {
                const uint32_t b0 = smw[KS2_OFF + kv_idx(kb + tg,     nbase + nb * 8 + g)];
                const uint32_t b1 = smw[KS2_OFF + kv_idx(kb + tg + 4, nbase + nb * 8 + g)];
                mma16816(acc[nb], a0, a1, a2, a3, b0, b1);
            }
        }

        // ---- cap + mask in-frag ----
        const int mA = m0 + g, mB = m0 + g + 8;
        const int qiA = row0 + half * 64 + mA;
        const int qiB = row0 + half * 64 + mB;
        #pragma unroll
        for (int nb = 0; nb < 8; nb++) {
            #pragma unroll
            for (int c = 0; c < 4; c++) {
                const int n_ = nbase + nb * 8 + 2 * tg + (c & 1);
                const int kj = bidkv * BKV + n_;
                const int qi = (c < 2) ? qiA : qiB;
                const float lg = CAPV * tanhf(acc[nb][c] * (SCL / CAPV));
                const bool allowed = (kj <= qi) && (kj >= qi - WIN) && (qi < SEQ) && (kj < SEQ);
                acc[nb][c] = allowed ? lg : -INFINITY;
            }
        }

        // ---- softmax: per-row max (tg-shfl + 2-warp smem combine) ----
        float pmA = -INFINITY, pmB = -INFINITY;
        #pragma unroll
        for (int nb = 0; nb < 8; nb++) {
            pmA = fmaxf(pmA, fmaxf(acc[nb][0], acc[nb][1]));
            pmB = fmaxf(pmB, fmaxf(acc[nb][2], acc[nb][3]));
        }
        pmA = fmaxf(pmA, __shfl_xor_sync(0xffffffffu, pmA, 1));
        pmA = fmaxf(pmA, __shfl_xor_sync(0xffffffffu, pmA, 2));
        pmB = fmaxf(pmB, __shfl_xor_sync(0xffffffffu, pmB, 1));
        pmB = fmaxf(pmB, __shfl_xor_sync(0xffffffffu, pmB, 2));
        if (tg == 0) {
            smf[PARTM_OFF + wn * 64 + mA] = pmA;
            smf[PARTM_OFF + wn * 64 + mB] = pmB;
        }
        __syncthreads();
        const float rowMA = fmaxf(smf[PARTM_OFF + mA], smf[PARTM_OFF + 64 + mA]);
        const float rowMB = fmaxf(smf[PARTM_OFF + mB], smf[PARTM_OFF + 64 + mB]);

        // ---- e = exp(x - rowmax), partial sums, write P (bf16x2) into Ps2 ----
        float psA = 0.0f, psB = 0.0f;
        #pragma unroll
        for (int nb = 0; nb < 8; nb++) {
            float e0 = (rowMA == -INFINITY) ? 0.0f : expf(acc[nb][0] - rowMA);
            float e1 = (rowMA == -INFINITY) ? 0.0f : expf(acc[nb][1] - rowMA);
            float e2 = (rowMB == -INFINITY) ? 0.0f : expf(acc[nb][2] - rowMB);
            float e3 = (rowMB == -INFINITY) ? 0.0f : expf(acc[nb][3] - rowMB);
            psA += e0 + e1;
            psB += e2 + e3;
            const int kp = (nbase >> 1) + nb * 4 + tg;
            smw[PS2_OFF + qp_idx(kp, mA)] = pack_bf16x2(e0, e1);
            smw[PS2_OFF + qp_idx(kp, mB)] = pack_bf16x2(e2, e3);
        }
        psA += __shfl_xor_sync(0xffffffffu, psA, 1);
        psA += __shfl_xor_sync(0xffffffffu, psA, 2);
        psB += __shfl_xor_sync(0xffffffffu, psB, 1);
        psB += __shfl_xor_sync(0xffffffffu, psB, 2);
        if (tg == 0) {
            smf[PARTS_OFF + wn * 64 + mA] = psA;
            smf[PARTS_OFF + wn * 64 + mB] = psB;
        }
        __syncthreads();

        // ---- per-row merge scalars (one thread per row) ----
        if (tg == 0 && wn == 0) {
            #pragma unroll
            for (int rsel = 0; rsel < 2; rsel++) {
                const int m_  = rsel ? mB : mA;
                const float rowM = rsel ? rowMB : rowMA;
                const float ssum = smf[PARTS_OFF + m_] + smf[PARTS_OFF + 64 + m_];
                const float lb = (ssum > 0.0f) ? (rowM + logf(ssum)) : -INFINITY;
                const int s = row0 + half * 64 + m_;
                const float lse_old = glse[((size_t)batch * HQ + h) * SEQ + s];
                const float mx = fmaxf(lse_old, lb);
                const float lse_new = (mx == -INFINITY) ? -INFINITY
                                     : mx + log1pf(expf(fminf(lse_old, lb) - mx));
                const bool fin = isfinite(lse_new);
                smf[SOLD_OFF + m_] = fin ? expf(lse_old - lse_new) : 0.0f;
                smf[SCB_OFF  + m_] = fin ? expf(rowM - lse_new)    : 0.0f;  // absorbs 1/sum
                out[O_ELEMS + ((size_t)batch * HQ + h) * SEQ + s] = lse_new;
            }
        }
        __syncthreads();

        // ---- GEMM2: O[64][128] = P * V via mma.m16n8k16 ----
        float oacc[8][4];
        #pragma unroll
        for (int nb = 0; nb < 8; nb++)
            #pragma unroll
            for (int c = 0; c < 4; c++) oacc[nb][c] = 0.0f;

        #pragma unroll
        for (int ks = 0; ks < 8; ks++) {
            const int kb = ks * 8;
            const uint32_t a0 = smw[PS2_OFF + qp_idx(kb + tg,     m0 + g)];
            const uint32_t a1 = smw[PS2_OFF + qp_idx(kb + tg,     m0 + g + 8)];
            const uint32_t a2 = smw[PS2_OFF + qp_idx(kb + tg + 4, m0 + g)];
            const uint32_t a3 = smw[PS2_OFF + qp_idx(kb + tg + 4, m0 + g + 8)];
            #pragma unroll
            for (int nb = 0; nb < 8; nb++) {
                const uint32_t b0 = smw[VS2_OFF + kv_idx(kb + tg,     nbase + nb * 8 + g)];
                const uint32_t b1 = smw[VS2_OFF + kv_idx(kb + tg + 4, nbase + nb * 8 + g)];
                mma16816(oacc[nb], a0, a1, a2, a3, b0, b1);
            }
        }

        // ---- online merge + writeout (float2 per row-pair fragment) ----
        const float coldA = smf[SOLD_OFF + mA], cbA = smf[SCB_OFF + mA];
        const float coldB = smf[SOLD_OFF + mB], cbB = smf[SCB_OFF + mB];
        const int sA_ = row0 + half * 64 + mA;
        const int sB_ = row0 + half * 64 + mB;
        const size_t baseA = (((size_t)batch * SEQ + sA_) * HQ + h) * HD;
        const size_t baseB = (((size_t)batch * SEQ + sB_) * HQ + h) * HD;
        #pragma unroll
        for (int nb = 0; nb < 8; nb++) {
            const int d0 = nbase + nb * 8 + 2 * tg;
            const float2 ooA = *(const float2*)(go + baseA + d0);
            const float2 ooB = *(const float2*)(go + baseB + d0);
            float2 wA, wB;
            wA.x = coldA * ooA.x + cbA * oacc[nb][0];
            wA.y = coldA * ooA.y + cbA * oacc[nb][1];
            wB.x = coldB * ooB.x + cbB * oacc[nb][2];
            wB.y = coldB * ooB.y + cbB * oacc[nb][3];
            *(float2*)(out + baseA + d0) = wA;
            *(float2*)(out + baseB + d0) = wB;
        }
    }

    // ---------------- dynamic copy of the remaining output regions ----------------
    // Pipelined work queue: prefetch the next chunk id while copying the current.
    {
        int par = 0;
        if (t == 0) s_chunk2[0] = atomicAdd(&g_chunk_counter, 1);
        __syncthreads();
        while (true) {
            const int c = s_chunk2[par];
            if (t == 0) s_chunk2[par ^ 1] = atomicAdd(&g_chunk_counter, 1);
            if (c >= nChunkTotal) break;
            copy_chunk(cc, c, t);
            __syncthreads();   // publish prefetched id; all threads done with c
            par ^= 1;
        }
    }

    // ---------------- self-reset for the next graph replay ----------------
    // Every CTA's final chunk-atomic strictly precedes its done-increment, so
    // the CTA observing done == gridDim.x - 1 runs after ALL queue atomics and
    // can safely zero the counters for the next launch.
    if (t == 0) {
        __threadfence();
        const int nd = atomicAdd(&g_done_counter, 1);
        if (nd == (int)gridDim.x - 1) {
            atomicExch(&g_chunk_counter, 0);
            atomicExch(&g_done_counter, 0);
            __threadfence();
        }
    }
}

extern "C" void kernel_launch(void* const* d_in, const int* in_sizes, int n_in,
                              void* d_out, int out_size)
{
    const float* q    = (const float*)d_in[0];
    const float* k    = (const float*)d_in[1];
    const float* v    = (const float*)d_in[2];
    const float* go   = (const float*)d_in[3];
    const float* glse = (const float*)d_in[4];
    const float* gq   = (const float*)d_in[5];
    const float* gk   = (const float*)d_in[6];
    const int*   biq  = (const int*)d_in[7];
    const int*   bikv = (const int*)d_in[8];
    float* out = (float*)d_out;

    const int B = in_sizes[0] / (BQ * HQ * HD);                 // 4
    const int nCompute    = B * HQ * 2;                         // 256
    const int nChunkO     = (B * (SEQ - BQ)) / ROWS_PER_CHUNK;  // 3968
    const int nChunkTotal = nChunkO + B * HQ;                   // +128 lse chunks

    const size_t smem = SMEM_WORDS * sizeof(uint32_t);          // ~83.5 KB
    cudaFuncSetAttribute(oswa_fused_kernel,
                         cudaFuncAttributeMaxDynamicSharedMemorySize, (int)smem);

    const int grid = nCompute + 40;   // 296 = 2 CTAs/SM * 148 SMs

    oswa_fused_kernel<<<grid, 256, smem>>>(q, k, v, go, glse, gq, gk, biq, bikv,
                                           out, B, nCompute, nChunkO, nChunkTotal);
}

// round 14
// speedup vs baseline: 1.1081x; 1.1081x over previous
#include <cuda_runtime.h>
#include <math.h>
#include <stdint.h>

// Problem constants (fixed by the reference)
#define HD    128
#define HQ    32
#define HKV   8
#define SEQ   4096
#define BQ    128
#define BKV   128
#define WIN   512
#define CAPV  50.0f
#define EPSV  1e-5f
#define SCL   0.08838834764831845f   // 1/sqrt(128)

#define ROWS_PER_CHUNK 8
#define N_PRE 3

// ---- shared memory layout (32-bit words) ----
#define KS2_OFF   0
#define VS2_OFF   8192
#define QS2_OFF   16384
#define PS2_OFF   16384
#define PARTM_OFF 20480
#define PARTS_OFF 20608
#define SOLD_OFF  20736
#define SCB_OFF   20800
#define SMEM_WORDS 20880

__device__ int g_chunk_counter;
__global__ void init_counter_kernel() { g_chunk_counter = 0; }

__device__ __forceinline__ int kv_idx(int kp, int col) {   // stride-128 arrays
    return kp * 128 + (col ^ ((kp & 3) << 3));
}
__device__ __forceinline__ int qp_idx(int kp, int col) {   // stride-64 arrays
    return kp * 64 + (col ^ ((kp & 3) << 3));
}

__device__ __forceinline__ uint32_t pack_bf16x2(float lo, float hi) {
    uint32_t r;
    asm("cvt.rn.bf16x2.f32 %0, %1, %2;" : "=r"(r) : "f"(hi), "f"(lo));
    return r;
}

__device__ __forceinline__ void mma16816(float* c,
    uint32_t a0, uint32_t a1, uint32_t a2, uint32_t a3,
    uint32_t b0, uint32_t b1)
{
    asm volatile(
        "mma.sync.aligned.m16n8k16.row.col.f32.bf16.bf16.f32 "
        "{%0,%1,%2,%3}, {%4,%5,%6,%7}, {%8,%9}, {%0,%1,%2,%3};"
        : "+f"(c[0]), "+f"(c[1]), "+f"(c[2]), "+f"(c[3])
        : "r"(a0), "r"(a1), "r"(a2), "r"(a3), "r"(b0), "r"(b1));
}

struct CopyCtx {
    const float4* src_o;
    float4*       dst_o;
    const float4* src_l;
    float4*       dst_l;
    int row0;
    int nChunkO;
};

// Copy one chunk c. Chunks < nChunkO are 8 full global_o rows (128KB);
// the rest are one (batch,head) lse row each, skipping the updated slice.
__device__ __forceinline__ void copy_chunk(const CopyCtx& cc, int c, int t)
{
    const int SROWS = SEQ - BQ;   // 3968
    if (c < cc.nChunkO) {
        const int vr0 = c * ROWS_PER_CHUNK;
        #pragma unroll
        for (int rr = 0; rr < ROWS_PER_CHUNK; rr += 2) {
            const int vrA = vr0 + rr, vrB = vr0 + rr + 1;
            const int bA = vrA / SROWS, bB = vrB / SROWS;
            const int sA0 = vrA - bA * SROWS, sB0 = vrB - bB * SROWS;
            const int sA = sA0 + (sA0 >= cc.row0 ? BQ : 0);
            const int sB = sB0 + (sB0 >= cc.row0 ? BQ : 0);
            const size_t rbA = (((size_t)bA * SEQ + sA) * HQ * HD) >> 2;
            const size_t rbB = (((size_t)bB * SEQ + sB) * HQ * HD) >> 2;
            float4 tmp[8];
            #pragma unroll
            for (int u = 0; u < 4; u++) tmp[u]     = __ldcs(cc.src_o + rbA + t + u * 256);
            #pragma unroll
            for (int u = 0; u < 4; u++) tmp[4 + u] = __ldcs(cc.src_o + rbB + t + u * 256);
            #pragma unroll
            for (int u = 0; u < 4; u++) __stcs(cc.dst_o + rbA + t + u * 256, tmp[u]);
            #pragma unroll
            for (int u = 0; u < 4; u++) __stcs(cc.dst_o + rbB + t + u * 256, tmp[4 + u]);
        }
    } else {
        const int hb = c - cc.nChunkO;
        const size_t base = (size_t)hb * SEQ;
        const int npos4 = SROWS >> 2;   // 992
        for (int p4 = t; p4 < npos4; p4 += 256) {
            const int p = p4 * 4;
            const int s = p + (p >= cc.row0 ? BQ : 0);
            __stcs(cc.dst_l + ((base + s) >> 2), __ldcs(cc.src_l + ((base + s) >> 2)));
        }
    }
}

__global__ __launch_bounds__(256, 2)
void oswa_fused_kernel(
    const float* __restrict__ q,   const float* __restrict__ k,
    const float* __restrict__ v,   const float* __restrict__ go,
    const float* __restrict__ glse,
    const float* __restrict__ gq,  const float* __restrict__ gk,
    const int* __restrict__ biq,   const int* __restrict__ bikv,
    float* __restrict__ out,
    int B, int nComputeBlocks, int nChunkO, int nChunkTotal)
{
    extern __shared__ uint32_t smw[];
    float* smf = (float*)smw;
    __shared__ int s_chunk;

    const int t    = threadIdx.x;
    const int lane = t & 31;
    const int w    = t >> 5;

    const int bidq  = biq[0];
    const int bidkv = bikv[0];
    const int row0  = bidq * BQ;
    const size_t O_ELEMS = (size_t)B * SEQ * HQ * HD;

    CopyCtx cc;
    cc.src_o = (const float4*)go;
    cc.dst_o = (float4*)out;
    cc.src_l = (const float4*)glse;
    cc.dst_l = (float4*)(out + O_ELEMS);
    cc.row0  = row0;
    cc.nChunkO = nChunkO;

    const int bid = blockIdx.x;

    if (bid < nComputeBlocks) {
        if (bid >= 148) {
            // stagger: second co-resident CTA copies N_PRE chunks first so DRAM
            // stays fed while its partner CTA runs the attention compute.
            for (int it = 0; it < N_PRE; it++) {
                if (t == 0) s_chunk = atomicAdd(&g_chunk_counter, 1);
                __syncthreads();
                const int c = s_chunk;
                __syncthreads();
                if (c < nChunkTotal) copy_chunk(cc, c, t);
                else break;
            }
        }

        // ---------------- attention tile: (batch, head, q-half of 64 rows) ----------------
        const int half  = bid & 1;
        const int h     = (bid >> 1) % HQ;
        const int batch = bid / (2 * HQ);
        const int kh    = h / (HQ / HKV);

        const int r4 = lane & 3;      // row-offset within 4-row group (loaders)
        const int qd = lane >> 2;     // d-group (loaders)

        // ---- K: load + RMSNorm + pack -> Ks2[kpair][j]  (4 rows/warp/iter, 4 iters) ----
        {
            #pragma unroll
            for (int it = 0; it < 4; it++) {
                const int j = it * 32 + w * 4 + r4;
                const float* kr = k + (((size_t)batch * BKV + j) * HKV + kh) * HD;
                float2 xv[8];
                float ss = 0.0f;
                #pragma unroll
                for (int p = 0; p < 8; p++) {
                    xv[p] = *(const float2*)(kr + 2 * qd + 16 * p);
                    ss += xv[p].x * xv[p].x + xv[p].y * xv[p].y;
                }
                ss += __shfl_xor_sync(0xffffffffu, ss, 4);
                ss += __shfl_xor_sync(0xffffffffu, ss, 8);
                ss += __shfl_xor_sync(0xffffffffu, ss, 16);
                const float rstd = rsqrtf(ss * (1.0f / HD) + EPSV);
                #pragma unroll
                for (int p = 0; p < 8; p++) {
                    const float2 g2 = *(const float2*)(gk + kh * HD + 2 * qd + 16 * p);
                    const int kp = qd + 8 * p;
                    smw[KS2_OFF + kv_idx(kp, j)] =
                        pack_bf16x2(xv[p].x * rstd * g2.x, xv[p].y * rstd * g2.y);
                }
            }
        }
        // ---- Q: load + RMSNorm + pack -> Qs2[kpair][i]  (2 iters) ----
        {
            #pragma unroll
            for (int it = 0; it < 2; it++) {
                const int i = it * 32 + w * 4 + r4;
                const int qrow = half * 64 + i;
                const float* qr = q + (((size_t)batch * BQ + qrow) * HQ + h) * HD;
                float2 xv[8];
                float ss = 0.0f;
                #pragma unroll
                for (int p = 0; p < 8; p++) {
                    xv[p] = *(const float2*)(qr + 2 * qd + 16 * p);
                    ss += xv[p].x * xv[p].x + xv[p].y * xv[p].y;
                }
                ss += __shfl_xor_sync(0xffffffffu, ss, 4);
                ss += __shfl_xor_sync(0xffffffffu, ss, 8);
                ss += __shfl_xor_sync(0xffffffffu, ss, 16);
                const float rstd = rsqrtf(ss * (1.0f / HD) + EPSV);
                #pragma unroll
                for (int p = 0; p < 8; p++) {
                    const float2 g2 = *(const float2*)(gq + h * HD + 2 * qd + 16 * p);
                    const int kp = qd + 8 * p;
                    smw[QS2_OFF + qp_idx(kp, i)] =
                        pack_bf16x2(xv[p].x * rstd * g2.x, xv[p].y * rstd * g2.y);
                }
            }
        }
        // ---- V: load + pack pairs along j -> Vs2[jpair][d]  (2 iters) ----
        {
            #pragma unroll
            for (int it = 0; it < 2; it++) {
                const int jp = it * 32 + w * 4 + r4;
                const float* v0 = v + (((size_t)batch * BKV + 2 * jp) * HKV + kh) * HD;
                const float* v1 = v0 + (size_t)HKV * HD;
                #pragma unroll
                for (int p = 0; p < 8; p++) {
                    const int d0 = 2 * qd + 16 * p;
                    const float2 f0 = *(const float2*)(v0 + d0);
                    const float2 f1 = *(const float2*)(v1 + d0);
                    const int idx = VS2_OFF + kv_idx(jp, d0);   // d0 even -> idx,idx+1 contiguous
                    uint2 wv;
                    wv.x = pack_bf16x2(f0.x, f1.x);
                    wv.y = pack_bf16x2(f0.y, f1.y);
                    *(uint2*)(smw + idx) = wv;
                }
            }
        }
        __syncthreads();

        // ---- GEMM1: S[64][128] = Qn * Kn^T via mma.m16n8k16 ----
        const int g   = lane >> 2;     // 0..7
        const int tg  = lane & 3;      // 0..3
        const int wm  = w & 3;
        const int wn  = w >> 2;
        const int m0  = wm * 16;
        const int nbase = wn * 64;

        float acc[8][4];
        #pragma unroll
        for (int nb = 0; nb < 8; nb++)
            #pragma unroll
            for (int c = 0; c < 4; c++) acc[nb][c] = 0.0f;

        #pragma unroll
        for (int ks = 0; ks < 8; ks++) {
            const int kb = ks * 8;
            const uint32_t a0 = smw[QS2_OFF + qp_idx(kb + tg,     m0 + g)];
            const uint32_t a1 = smw[QS2_OFF + qp_idx(kb + tg,     m0 + g + 8)];
            const uint32_t a2 = smw[QS2_OFF + qp_idx(kb + tg + 4, m0 + g)];
            const uint32_t a3 = smw[QS2_OFF + qp_idx(kb + tg + 4, m0 + g + 8)];
            #pragma unroll
            for (int nb = 0; nb < 8; nb++) {
                const uint32_t b0 = smw[KS2_OFF + kv_idx(kb + tg,     nbase + nb * 8 + g)];
                const uint32_t b1 = smw[KS2_OFF + kv_idx(kb + tg + 4, nbase + nb * 8 + g)];
                mma16816(acc[nb], a0, a1, a2, a3, b0, b1);
            }
        }

        // ---- cap + mask in-frag ----
        const int mA = m0 + g, mB = m0 + g + 8;
        const int qiA = row0 + half * 64 + mA;
        const int qiB = row0 + half * 64 + mB;
        #pragma unroll
        for (int nb = 0; nb < 8; nb++) {
            #pragma unroll
            for (int c = 0; c < 4; c++) {
                const int n_ = nbase + nb * 8 + 2 * tg + (c & 1);
                const int kj = bidkv * BKV + n_;
                const int qi = (c < 2) ? qiA : qiB;
                const float lg = CAPV * tanhf(acc[nb][c] * (SCL / CAPV));
                const bool allowed = (kj <= qi) && (kj >= qi - WIN) && (qi < SEQ) && (kj < SEQ);
                acc[nb][c] = allowed ? lg : -INFINITY;
            }
        }

        // ---- softmax: per-row max (tg-shfl + 2-warp smem combine) ----
        float pmA = -INFINITY, pmB = -INFINITY;
        #pragma unroll
        for (int nb = 0; nb < 8; nb++) {
            pmA = fmaxf(pmA, fmaxf(acc[nb][0], acc[nb][1]));
            pmB = fmaxf(pmB, fmaxf(acc[nb][2], acc[nb][3]));
        }
        pmA = fmaxf(pmA, __shfl_xor_sync(0xffffffffu, pmA, 1));
        pmA = fmaxf(pmA, __shfl_xor_sync(0xffffffffu, pmA, 2));
        pmB = fmaxf(pmB, __shfl_xor_sync(0xffffffffu, pmB, 1));
        pmB = fmaxf(pmB, __shfl_xor_sync(0xffffffffu, pmB, 2));
        if (tg == 0) {
            smf[PARTM_OFF + wn * 64 + mA] = pmA;
            smf[PARTM_OFF + wn * 64 + mB] = pmB;
        }
        __syncthreads();
        const float rowMA = fmaxf(smf[PARTM_OFF + mA], smf[PARTM_OFF + 64 + mA]);
        const float rowMB = fmaxf(smf[PARTM_OFF + mB], smf[PARTM_OFF + 64 + mB]);

        // ---- e = exp(x - rowmax), partial sums, write P (bf16x2) into Ps2 ----
        float psA = 0.0f, psB = 0.0f;
        #pragma unroll
        for (int nb = 0; nb < 8; nb++) {
            float e0 = (rowMA == -INFINITY) ? 0.0f : expf(acc[nb][0] - rowMA);
            float e1 = (rowMA == -INFINITY) ? 0.0f : expf(acc[nb][1] - rowMA);
            float e2 = (rowMB == -INFINITY) ? 0.0f : expf(acc[nb][2] - rowMB);
            float e3 = (rowMB == -INFINITY) ? 0.0f : expf(acc[nb][3] - rowMB);
            psA += e0 + e1;
            psB += e2 + e3;
            const int kp = (nbase >> 1) + nb * 4 + tg;
            smw[PS2_OFF + qp_idx(kp, mA)] = pack_bf16x2(e0, e1);
            smw[PS2_OFF + qp_idx(kp, mB)] = pack_bf16x2(e2, e3);
        }
        psA += __shfl_xor_sync(0xffffffffu, psA, 1);
        psA += __shfl_xor_sync(0xffffffffu, psA, 2);
        psB += __shfl_xor_sync(0xffffffffu, psB, 1);
        psB += __shfl_xor_sync(0xffffffffu, psB, 2);
        if (tg == 0) {
            smf[PARTS_OFF + wn * 64 + mA] = psA;
            smf[PARTS_OFF + wn * 64 + mB] = psB;
        }
        __syncthreads();

        // ---- per-row merge scalars (one thread per row) ----
        if (tg == 0 && wn == 0) {
            #pragma unroll
            for (int rsel = 0; rsel < 2; rsel++) {
                const int m_  = rsel ? mB : mA;
                const float rowM = rsel ? rowMB : rowMA;
                const float ssum = smf[PARTS_OFF + m_] + smf[PARTS_OFF + 64 + m_];
                const float lb = (ssum > 0.0f) ? (rowM + logf(ssum)) : -INFINITY;
                const int s = row0 + half * 64 + m_;
                const float lse_old = glse[((size_t)batch * HQ + h) * SEQ + s];
                const float mx = fmaxf(lse_old, lb);
                const float lse_new = (mx == -INFINITY) ? -INFINITY
                                     : mx + log1pf(expf(fminf(lse_old, lb) - mx));
                const bool fin = isfinite(lse_new);
                smf[SOLD_OFF + m_] = fin ? expf(lse_old - lse_new) : 0.0f;
                smf[SCB_OFF  + m_] = fin ? expf(rowM - lse_new)    : 0.0f;  // absorbs 1/sum
                out[O_ELEMS + ((size_t)batch * HQ + h) * SEQ + s] = lse_new;
            }
        }
        __syncthreads();

        // ---- GEMM2: O[64][128] = P * V via mma.m16n8k16 ----
        float oacc[8][4];
        #pragma unroll
        for (int nb = 0; nb < 8; nb++)
            #pragma unroll
            for (int c = 0; c < 4; c++) oacc[nb][c] = 0.0f;

        #pragma unroll
        for (int ks = 0; ks < 8; ks++) {
            const int kb = ks * 8;
            const uint32_t a0 = smw[PS2_OFF + qp_idx(kb + tg,     m0 + g)];
            const uint32_t a1 = smw[PS2_OFF + qp_idx(kb + tg,     m0 + g + 8)];
            const uint32_t a2 = smw[PS2_OFF + qp_idx(kb + tg + 4, m0 + g)];
            const uint32_t a3 = smw[PS2_OFF + qp_idx(kb + tg + 4, m0 + g + 8)];
            #pragma unroll
            for (int nb = 0; nb < 8; nb++) {
                const uint32_t b0 = smw[VS2_OFF + kv_idx(kb + tg,     nbase + nb * 8 + g)];
                const uint32_t b1 = smw[VS2_OFF + kv_idx(kb + tg + 4, nbase + nb * 8 + g)];
                mma16816(oacc[nb], a0, a1, a2, a3, b0, b1);
            }
        }

        // ---- online merge + writeout (float2 per row-pair fragment) ----
        const float coldA = smf[SOLD_OFF + mA], cbA = smf[SCB_OFF + mA];
        const float coldB = smf[SOLD_OFF + mB], cbB = smf[SCB_OFF + mB];
        const int sA_ = row0 + half * 64 + mA;
        const int sB_ = row0 + half * 64 + mB;
        const size_t baseA = (((size_t)batch * SEQ + sA_) * HQ + h) * HD;
        const size_t baseB = (((size_t)batch * SEQ + sB_) * HQ + h) * HD;
        #pragma unroll
        for (int nb = 0; nb < 8; nb++) {
            const int d0 = nbase + nb * 8 + 2 * tg;
            const float2 ooA = *(const float2*)(go + baseA + d0);
            const float2 ooB = *(const float2*)(go + baseB + d0);
            float2 wA, wB;
            wA.x = coldA * ooA.x + cbA * oacc[nb][0];
            wA.y = coldA * ooA.y + cbA * oacc[nb][1];
            wB.x = coldB * ooB.x + cbB * oacc[nb][2];
            wB.y = coldB * ooB.y + cbB * oacc[nb][3];
            *(float2*)(out + baseA + d0) = wA;
            *(float2*)(out + baseB + d0) = wB;
        }
    }

    // ---------------- dynamic copy of the remaining output regions ----------------
    while (true) {
        if (t == 0) s_chunk = atomicAdd(&g_chunk_counter, 1);
        __syncthreads();
        const int c = s_chunk;
        __syncthreads();
        if (c >= nChunkTotal) break;
        copy_chunk(cc, c, t);
    }
}

extern "C" void kernel_launch(void* const* d_in, const int* in_sizes, int n_in,
                              void* d_out, int out_size)
{
    const float* q    = (const float*)d_in[0];
    const float* k    = (const float*)d_in[1];
    const float* v    = (const float*)d_in[2];
    const float* go   = (const float*)d_in[3];
    const float* glse = (const float*)d_in[4];
    const float* gq   = (const float*)d_in[5];
    const float* gk   = (const float*)d_in[6];
    const int*   biq  = (const int*)d_in[7];
    const int*   bikv = (const int*)d_in[8];
    float* out = (float*)d_out;

    const int B = in_sizes[0] / (BQ * HQ * HD);                 // 4
    const int nCompute    = B * HQ * 2;                         // 256
    const int nChunkO     = (B * (SEQ - BQ)) / ROWS_PER_CHUNK;  // 1984
    const int nChunkTotal = nChunkO + B * HQ;                   // +128 lse chunks

    const size_t smem = SMEM_WORDS * sizeof(uint32_t);          // ~83.5 KB
    cudaFuncSetAttribute(oswa_fused_kernel,
                         cudaFuncAttributeMaxDynamicSharedMemorySize, (int)smem);

    const int grid = nCompute + 40;   // 296 = 2 CTAs/SM * 148 SMs

    init_counter_kernel<<<1, 1>>>();
    oswa_fused_kernel<<<grid, 256, smem>>>(q, k, v, go, glse, gq, gk, biq, bikv,
                                           out, B, nCompute, nChunkO, nChunkTotal);
}

// round 15
// speedup vs baseline: 1.1088x; 1.0007x over previous
#include <cuda_runtime.h>
#include <math.h>
#include <stdint.h>

// Problem constants (fixed by the reference)
#define HD    128
#define HQ    32
#define HKV   8
#define SEQ   4096
#define BQ    128
#define BKV   128
#define WIN   512
#define CAPV  50.0f
#define EPSV  1e-5f
#define SCL   0.08838834764831845f   // 1/sqrt(128)

#define ROWS_PER_CHUNK 8
#define N_PRE 3

// ---- shared memory layout (32-bit words) ----
#define KS2_OFF   0
#define VS2_OFF   8192
#define QS2_OFF   16384
#define PS2_OFF   16384
#define PARTM_OFF 20480
#define PARTS_OFF 20608
#define SOLD_OFF  20736
#define SCB_OFF   20800
#define SMEM_WORDS 20880

// Monotonic work-queue counter. NEVER reset: each launch consumes exactly
// K = nChunkTotal + gridDim.x increments (every non-terminal chunk id copied
// exactly once; exactly one terminal draw per CTA), so chunk id = raw % K is
// replay-deterministic without an init kernel.
__device__ unsigned int g_chunk_counter;

__device__ __forceinline__ int kv_idx(int kp, int col) {   // stride-128 arrays
    return kp * 128 + (col ^ ((kp & 3) << 3));
}
__device__ __forceinline__ int qp_idx(int kp, int col) {   // stride-64 arrays
    return kp * 64 + (col ^ ((kp & 3) << 3));
}

__device__ __forceinline__ uint32_t pack_bf16x2(float lo, float hi) {
    uint32_t r;
    asm("cvt.rn.bf16x2.f32 %0, %1, %2;" : "=r"(r) : "f"(hi), "f"(lo));
    return r;
}

__device__ __forceinline__ void mma16816(float* c,
    uint32_t a0, uint32_t a1, uint32_t a2, uint32_t a3,
    uint32_t b0, uint32_t b1)
{
    asm volatile(
        "mma.sync.aligned.m16n8k16.row.col.f32.bf16.bf16.f32 "
        "{%0,%1,%2,%3}, {%4,%5,%6,%7}, {%8,%9}, {%0,%1,%2,%3};"
        : "+f"(c[0]), "+f"(c[1]), "+f"(c[2]), "+f"(c[3])
        : "r"(a0), "r"(a1), "r"(a2), "r"(a3), "r"(b0), "r"(b1));
}

struct CopyCtx {
    const float4* src_o;
    float4*       dst_o;
    const float4* src_l;
    float4*       dst_l;
    int row0;
    int nChunkO;
};

// Copy one chunk c. Chunks < nChunkO are 8 full global_o rows (128KB);
// the rest are one (batch,head) lse row each, skipping the updated slice.
__device__ __forceinline__ void copy_chunk(const CopyCtx& cc, int c, int t)
{
    const int SROWS = SEQ - BQ;   // 3968
    if (c < cc.nChunkO) {
        const int vr0 = c * ROWS_PER_CHUNK;
        #pragma unroll
        for (int rr = 0; rr < ROWS_PER_CHUNK; rr += 2) {
            const int vrA = vr0 + rr, vrB = vr0 + rr + 1;
            const int bA = vrA / SROWS, bB = vrB / SROWS;
            const int sA0 = vrA - bA * SROWS, sB0 = vrB - bB * SROWS;
            const int sA = sA0 + (sA0 >= cc.row0 ? BQ : 0);
            const int sB = sB0 + (sB0 >= cc.row0 ? BQ : 0);
            const size_t rbA = (((size_t)bA * SEQ + sA) * HQ * HD) >> 2;
            const size_t rbB = (((size_t)bB * SEQ + sB) * HQ * HD) >> 2;
            float4 tmp[8];
            #pragma unroll
            for (int u = 0; u < 4; u++) tmp[u]     = __ldcs(cc.src_o + rbA + t + u * 256);
            #pragma unroll
            for (int u = 0; u < 4; u++) tmp[4 + u] = __ldcs(cc.src_o + rbB + t + u * 256);
            #pragma unroll
            for (int u = 0; u < 4; u++) __stcs(cc.dst_o + rbA + t + u * 256, tmp[u]);
            #pragma unroll
            for (int u = 0; u < 4; u++) __stcs(cc.dst_o + rbB + t + u * 256, tmp[4 + u]);
        }
    } else {
        const int hb = c - cc.nChunkO;
        const size_t base = (size_t)hb * SEQ;
        const int npos4 = SROWS >> 2;   // 992
        for (int p4 = t; p4 < npos4; p4 += 256) {
            const int p = p4 * 4;
            const int s = p + (p >= cc.row0 ? BQ : 0);
            __stcs(cc.dst_l + ((base + s) >> 2), __ldcs(cc.src_l + ((base + s) >> 2)));
        }
    }
}

__global__ __launch_bounds__(256, 2)
void oswa_fused_kernel(
    const float* __restrict__ q,   const float* __restrict__ k,
    const float* __restrict__ v,   const float* __restrict__ go,
    const float* __restrict__ glse,
    const float* __restrict__ gq,  const float* __restrict__ gk,
    const int* __restrict__ biq,   const int* __restrict__ bikv,
    float* __restrict__ out,
    int B, int nComputeBlocks, int nChunkO, int nChunkTotal, unsigned int qK)
{
    extern __shared__ uint32_t smw[];
    float* smf = (float*)smw;
    __shared__ int s_chunk;

    const int t    = threadIdx.x;
    const int lane = t & 31;
    const int w    = t >> 5;

    const int bidq  = biq[0];
    const int bidkv = bikv[0];
    const int row0  = bidq * BQ;
    const size_t O_ELEMS = (size_t)B * SEQ * HQ * HD;

    CopyCtx cc;
    cc.src_o = (const float4*)go;
    cc.dst_o = (float4*)out;
    cc.src_l = (const float4*)glse;
    cc.dst_l = (float4*)(out + O_ELEMS);
    cc.row0  = row0;
    cc.nChunkO = nChunkO;

    const int bid = blockIdx.x;
    bool terminated = false;   // this CTA has consumed its terminal queue slot

    if (bid < nComputeBlocks) {
        if (bid >= 148) {
            // stagger: second co-resident CTA copies N_PRE chunks first so DRAM
            // stays fed while its partner CTA runs the attention compute.
            for (int it = 0; it < N_PRE && !terminated; it++) {
                if (t == 0) s_chunk = (int)(atomicAdd(&g_chunk_counter, 1u) % qK);
                __syncthreads();
                const int c = s_chunk;
                __syncthreads();
                if (c < nChunkTotal) copy_chunk(cc, c, t);
                else terminated = true;
            }
        }

        // ---------------- attention tile: (batch, head, q-half of 64 rows) ----------------
        const int half  = bid & 1;
        const int h     = (bid >> 1) % HQ;
        const int batch = bid / (2 * HQ);
        const int kh    = h / (HQ / HKV);

        const int r4 = lane & 3;      // row-offset within 4-row group (loaders)
        const int qd = lane >> 2;     // d-group (loaders)

        // ---- K: load + RMSNorm + pack -> Ks2[kpair][j]  (4 rows/warp/iter, 4 iters) ----
        {
            #pragma unroll
            for (int it = 0; it < 4; it++) {
                const int j = it * 32 + w * 4 + r4;
                const float* kr = k + (((size_t)batch * BKV + j) * HKV + kh) * HD;
                float2 xv[8];
                float ss = 0.0f;
                #pragma unroll
                for (int p = 0; p < 8; p++) {
                    xv[p] = *(const float2*)(kr + 2 * qd + 16 * p);
                    ss += xv[p].x * xv[p].x + xv[p].y * xv[p].y;
                }
                ss += __shfl_xor_sync(0xffffffffu, ss, 4);
                ss += __shfl_xor_sync(0xffffffffu, ss, 8);
                ss += __shfl_xor_sync(0xffffffffu, ss, 16);
                const float rstd = rsqrtf(ss * (1.0f / HD) + EPSV);
                #pragma unroll
                for (int p = 0; p < 8; p++) {
                    const float2 g2 = *(const float2*)(gk + kh * HD + 2 * qd + 16 * p);
                    const int kp = qd + 8 * p;
                    smw[KS2_OFF + kv_idx(kp, j)] =
                        pack_bf16x2(xv[p].x * rstd * g2.x, xv[p].y * rstd * g2.y);
                }
            }
        }
        // ---- Q: load + RMSNorm + pack -> Qs2[kpair][i]  (2 iters) ----
        {
            #pragma unroll
            for (int it = 0; it < 2; it++) {
                const int i = it * 32 + w * 4 + r4;
                const int qrow = half * 64 + i;
                const float* qr = q + (((size_t)batch * BQ + qrow) * HQ + h) * HD;
                float2 xv[8];
                float ss = 0.0f;
                #pragma unroll
                for (int p = 0; p < 8; p++) {
                    xv[p] = *(const float2*)(qr + 2 * qd + 16 * p);
                    ss += xv[p].x * xv[p].x + xv[p].y * xv[p].y;
                }
                ss += __shfl_xor_sync(0xffffffffu, ss, 4);
                ss += __shfl_xor_sync(0xffffffffu, ss, 8);
                ss += __shfl_xor_sync(0xffffffffu, ss, 16);
                const float rstd = rsqrtf(ss * (1.0f / HD) + EPSV);
                #pragma unroll
                for (int p = 0; p < 8; p++) {
                    const float2 g2 = *(const float2*)(gq + h * HD + 2 * qd + 16 * p);
                    const int kp = qd + 8 * p;
                    smw[QS2_OFF + qp_idx(kp, i)] =
                        pack_bf16x2(xv[p].x * rstd * g2.x, xv[p].y * rstd * g2.y);
                }
            }
        }
        // ---- V: load + pack pairs along j -> Vs2[jpair][d]  (2 iters) ----
        {
            #pragma unroll
            for (int it = 0; it < 2; it++) {
                const int jp = it * 32 + w * 4 + r4;
                const float* v0 = v + (((size_t)batch * BKV + 2 * jp) * HKV + kh) * HD;
                const float* v1 = v0 + (size_t)HKV * HD;
                #pragma unroll
                for (int p = 0; p < 8; p++) {
                    const int d0 = 2 * qd + 16 * p;
                    const float2 f0 = *(const float2*)(v0 + d0);
                    const float2 f1 = *(const float2*)(v1 + d0);
                    const int idx = VS2_OFF + kv_idx(jp, d0);   // d0 even -> idx,idx+1 contiguous
                    uint2 wv;
                    wv.x = pack_bf16x2(f0.x, f1.x);
                    wv.y = pack_bf16x2(f0.y, f1.y);
                    *(uint2*)(smw + idx) = wv;
                }
            }
        }
        __syncthreads();

        // ---- GEMM1: S[64][128] = Qn * Kn^T via mma.m16n8k16 ----
        const int g   = lane >> 2;     // 0..7
        const int tg  = lane & 3;      // 0..3
        const int wm  = w & 3;
        const int wn  = w >> 2;
        const int m0  = wm * 16;
        const int nbase = wn * 64;

        float acc[8][4];
        #pragma unroll
        for (int nb = 0; nb < 8; nb++)
            #pragma unroll
            for (int c = 0; c < 4; c++) acc[nb][c] = 0.0f;

        #pragma unroll
        for (int ks = 0; ks < 8; ks++) {
            const int kb = ks * 8;
            const uint32_t a0 = smw[QS2_OFF + qp_idx(kb + tg,     m0 + g)];
            const uint32_t a1 = smw[QS2_OFF + qp_idx(kb + tg,     m0 + g + 8)];
            const uint32_t a2 = smw[QS2_OFF + qp_idx(kb + tg + 4, m0 + g)];
            const uint32_t a3 = smw[QS2_OFF + qp_idx(kb + tg + 4, m0 + g + 8)];
            #pragma unroll
            for (int nb = 0; nb < 8; nb++) {
                const uint32_t b0 = smw[KS2_OFF + kv_idx(kb + tg,     nbase + nb * 8 + g)];
                const uint32_t b1 = smw[KS2_OFF + kv_idx(kb + tg + 4, nbase + nb * 8 + g)];
                mma16816(acc[nb], a0, a1, a2, a3, b0, b1);
            }
        }

        // ---- cap + mask in-frag ----
        const int mA = m0 + g, mB = m0 + g + 8;
        const int qiA = row0 + half * 64 + mA;
        const int qiB = row0 + half * 64 + mB;
        #pragma unroll
        for (int nb = 0; nb < 8; nb++) {
            #pragma unroll
            for (int c = 0; c < 4; c++) {
                const int n_ = nbase + nb * 8 + 2 * tg + (c & 1);
                const int kj = bidkv * BKV + n_;
                const int qi = (c < 2) ? qiA : qiB;
                const float lg = CAPV * tanhf(acc[nb][c] * (SCL / CAPV));
                const bool allowed = (kj <= qi) && (kj >= qi - WIN) && (qi < SEQ) && (kj < SEQ);
                acc[nb][c] = allowed ? lg : -INFINITY;
            }
        }

        // ---- softmax: per-row max (tg-shfl + 2-warp smem combine) ----
        float pmA = -INFINITY, pmB = -INFINITY;
        #pragma unroll
        for (int nb = 0; nb < 8; nb++) {
            pmA = fmaxf(pmA, fmaxf(acc[nb][0], acc[nb][1]));
            pmB = fmaxf(pmB, fmaxf(acc[nb][2], acc[nb][3]));
        }
        pmA = fmaxf(pmA, __shfl_xor_sync(0xffffffffu, pmA, 1));
        pmA = fmaxf(pmA, __shfl_xor_sync(0xffffffffu, pmA, 2));
        pmB = fmaxf(pmB, __shfl_xor_sync(0xffffffffu, pmB, 1));
        pmB = fmaxf(pmB, __shfl_xor_sync(0xffffffffu, pmB, 2));
        if (tg == 0) {
            smf[PARTM_OFF + wn * 64 + mA] = pmA;
            smf[PARTM_OFF + wn * 64 + mB] = pmB;
        }
        __syncthreads();
        const float rowMA = fmaxf(smf[PARTM_OFF + mA], smf[PARTM_OFF + 64 + mA]);
        const float rowMB = fmaxf(smf[PARTM_OFF + mB], smf[PARTM_OFF + 64 + mB]);

        // ---- e = exp(x - rowmax), partial sums, write P (bf16x2) into Ps2 ----
        float psA = 0.0f, psB = 0.0f;
        #pragma unroll
        for (int nb = 0; nb < 8; nb++) {
            float e0 = (rowMA == -INFINITY) ? 0.0f : expf(acc[nb][0] - rowMA);
            float e1 = (rowMA == -INFINITY) ? 0.0f : expf(acc[nb][1] - rowMA);
            float e2 = (rowMB == -INFINITY) ? 0.0f : expf(acc[nb][2] - rowMB);
            float e3 = (rowMB == -INFINITY) ? 0.0f : expf(acc[nb][3] - rowMB);
            psA += e0 + e1;
            psB += e2 + e3;
            const int kp = (nbase >> 1) + nb * 4 + tg;
            smw[PS2_OFF + qp_idx(kp, mA)] = pack_bf16x2(e0, e1);
            smw[PS2_OFF + qp_idx(kp, mB)] = pack_bf16x2(e2, e3);
        }
        psA += __shfl_xor_sync(0xffffffffu, psA, 1);
        psA += __shfl_xor_sync(0xffffffffu, psA, 2);
        psB += __shfl_xor_sync(0xffffffffu, psB, 1);
        psB += __shfl_xor_sync(0xffffffffu, psB, 2);
        if (tg == 0) {
            smf[PARTS_OFF + wn * 64 + mA] = psA;
            smf[PARTS_OFF + wn * 64 + mB] = psB;
        }
        __syncthreads();

        // ---- per-row merge scalars (one thread per row) ----
        if (tg == 0 && wn == 0) {
            #pragma unroll
            for (int rsel = 0; rsel < 2; rsel++) {
                const int m_  = rsel ? mB : mA;
                const float rowM = rsel ? rowMB : rowMA;
                const float ssum = smf[PARTS_OFF + m_] + smf[PARTS_OFF + 64 + m_];
                const float lb = (ssum > 0.0f) ? (rowM + logf(ssum)) : -INFINITY;
                const int s = row0 + half * 64 + m_;
                const float lse_old = glse[((size_t)batch * HQ + h) * SEQ + s];
                const float mx = fmaxf(lse_old, lb);
                const float lse_new = (mx == -INFINITY) ? -INFINITY
                                     : mx + log1pf(expf(fminf(lse_old, lb) - mx));
                const bool fin = isfinite(lse_new);
                smf[SOLD_OFF + m_] = fin ? expf(lse_old - lse_new) : 0.0f;
                smf[SCB_OFF  + m_] = fin ? expf(rowM - lse_new)    : 0.0f;  // absorbs 1/sum
                out[O_ELEMS + ((size_t)batch * HQ + h) * SEQ + s] = lse_new;
            }
        }
        __syncthreads();

        // ---- GEMM2: O[64][128] = P * V via mma.m16n8k16 ----
        float oacc[8][4];
        #pragma unroll
        for (int nb = 0; nb < 8; nb++)
            #pragma unroll
            for (int c = 0; c < 4; c++) oacc[nb][c] = 0.0f;

        #pragma unroll
        for (int ks = 0; ks < 8; ks++) {
            const int kb = ks * 8;
            const uint32_t a0 = smw[PS2_OFF + qp_idx(kb + tg,     m0 + g)];
            const uint32_t a1 = smw[PS2_OFF + qp_idx(kb + tg,     m0 + g + 8)];
            const uint32_t a2 = smw[PS2_OFF + qp_idx(kb + tg + 4, m0 + g)];
            const uint32_t a3 = smw[PS2_OFF + qp_idx(kb + tg + 4, m0 + g + 8)];
            #pragma unroll
            for (int nb = 0; nb < 8; nb++) {
                const uint32_t b0 = smw[VS2_OFF + kv_idx(kb + tg,     nbase + nb * 8 + g)];
                const uint32_t b1 = smw[VS2_OFF + kv_idx(kb + tg + 4, nbase + nb * 8 + g)];
                mma16816(oacc[nb], a0, a1, a2, a3, b0, b1);
            }
        }

        // ---- online merge + writeout (float2 per row-pair fragment) ----
        const float coldA = smf[SOLD_OFF + mA], cbA = smf[SCB_OFF + mA];
        const float coldB = smf[SOLD_OFF + mB], cbB = smf[SCB_OFF + mB];
        const int sA_ = row0 + half * 64 + mA;
        const int sB_ = row0 + half * 64 + mB;
        const size_t baseA = (((size_t)batch * SEQ + sA_) * HQ + h) * HD;
        const size_t baseB = (((size_t)batch * SEQ + sB_) * HQ + h) * HD;
        #pragma unroll
        for (int nb = 0; nb < 8; nb++) {
            const int d0 = nbase + nb * 8 + 2 * tg;
            const float2 ooA = *(const float2*)(go + baseA + d0);
            const float2 ooB = *(const float2*)(go + baseB + d0);
            float2 wA, wB;
            wA.x = coldA * ooA.x + cbA * oacc[nb][0];
            wA.y = coldA * ooA.y + cbA * oacc[nb][1];
            wB.x = coldB * ooB.x + cbB * oacc[nb][2];
            wB.y = coldB * ooB.y + cbB * oacc[nb][3];
            *(float2*)(out + baseA + d0) = wA;
            *(float2*)(out + baseB + d0) = wB;
        }
    }

    // ---------------- dynamic copy of the remaining output regions ----------------
    while (!terminated) {
        if (t == 0) s_chunk = (int)(atomicAdd(&g_chunk_counter, 1u) % qK);
        __syncthreads();
        const int c = s_chunk;
        __syncthreads();
        if (c >= nChunkTotal) break;
        copy_chunk(cc, c, t);
    }
}

extern "C" void kernel_launch(void* const* d_in, const int* in_sizes, int n_in,
                              void* d_out, int out_size)
{
    const float* q    = (const float*)d_in[0];
    const float* k    = (const float*)d_in[1];
    const float* v    = (const float*)d_in[2];
    const float* go   = (const float*)d_in[3];
    const float* glse = (const float*)d_in[4];
    const float* gq   = (const float*)d_in[5];
    const float* gk   = (const float*)d_in[6];
    const int*   biq  = (const int*)d_in[7];
    const int*   bikv = (const int*)d_in[8];
    float* out = (float*)d_out;

    const int B = in_sizes[0] / (BQ * HQ * HD);                 // 4
    const int nCompute    = B * HQ * 2;                         // 256
    const int nChunkO     = (B * (SEQ - BQ)) / ROWS_PER_CHUNK;  // 1984
    const int nChunkTotal = nChunkO + B * HQ;                   // +128 lse chunks

    const size_t smem = SMEM_WORDS * sizeof(uint32_t);          // ~83.5 KB
    cudaFuncSetAttribute(oswa_fused_kernel,
                         cudaFuncAttributeMaxDynamicSharedMemorySize, (int)smem);

    const int grid = nCompute + 40;   // 296 = 2 CTAs/SM * 148 SMs
    const unsigned int qK = (unsigned int)(nChunkTotal + grid);  // atomics per launch

    oswa_fused_kernel<<<grid, 256, smem>>>(q, k, v, go, glse, gq, gk, biq, bikv,
                                           out, B, nCompute, nChunkO, nChunkTotal, qK);
}

// round 16
// speedup vs baseline: 1.1128x; 1.0035x over previous
#include <cuda_runtime.h>
#include <math.h>
#include <stdint.h>

// Problem constants (fixed by the reference)
#define HD    128
#define HQ    32
#define HKV   8
#define SEQ   4096
#define BQ    128
#define BKV   128
#define WIN   512
#define CAPV  50.0f
#define EPSV  1e-5f
#define SCL   0.08838834764831845f   // 1/sqrt(128)

#define ROWS_PER_CHUNK 8
#define N_PRE 5

// ---- shared memory layout (32-bit words) ----
#define KS2_OFF   0
#define VS2_OFF   8192
#define QS2_OFF   16384
#define PS2_OFF   16384
#define PARTM_OFF 20480
#define PARTS_OFF 20608
#define SOLD_OFF  20736
#define SCB_OFF   20800
#define SMEM_WORDS 20880

// Monotonic work-queue counter. NEVER reset: each launch consumes exactly
// K = nChunkTotal + gridDim.x increments (every non-terminal chunk id copied
// exactly once; exactly one terminal draw per CTA), so chunk id = raw % K is
// replay-deterministic without an init kernel.
__device__ unsigned int g_chunk_counter;

__device__ __forceinline__ int kv_idx(int kp, int col) {   // stride-128 arrays
    return kp * 128 + (col ^ ((kp & 3) << 3));
}
__device__ __forceinline__ int qp_idx(int kp, int col) {   // stride-64 arrays
    return kp * 64 + (col ^ ((kp & 3) << 3));
}

__device__ __forceinline__ uint32_t pack_bf16x2(float lo, float hi) {
    uint32_t r;
    asm("cvt.rn.bf16x2.f32 %0, %1, %2;" : "=r"(r) : "f"(hi), "f"(lo));
    return r;
}

__device__ __forceinline__ void mma16816(float* c,
    uint32_t a0, uint32_t a1, uint32_t a2, uint32_t a3,
    uint32_t b0, uint32_t b1)
{
    asm volatile(
        "mma.sync.aligned.m16n8k16.row.col.f32.bf16.bf16.f32 "
        "{%0,%1,%2,%3}, {%4,%5,%6,%7}, {%8,%9}, {%0,%1,%2,%3};"
        : "+f"(c[0]), "+f"(c[1]), "+f"(c[2]), "+f"(c[3])
        : "r"(a0), "r"(a1), "r"(a2), "r"(a3), "r"(b0), "r"(b1));
}

struct CopyCtx {
    const float4* src_o;
    float4*       dst_o;
    const float4* src_l;
    float4*       dst_l;
    int row0;
    int nChunkO;
};

// Copy one chunk c. Chunks < nChunkO are 8 full global_o rows (128KB);
// the rest are one (batch,head) lse row each, skipping the updated slice.
__device__ __forceinline__ void copy_chunk(const CopyCtx& cc, int c, int t)
{
    const int SROWS = SEQ - BQ;   // 3968
    if (c < cc.nChunkO) {
        const int vr0 = c * ROWS_PER_CHUNK;
        #pragma unroll
        for (int rr = 0; rr < ROWS_PER_CHUNK; rr += 2) {
            const int vrA = vr0 + rr, vrB = vr0 + rr + 1;
            const int bA = vrA / SROWS, bB = vrB / SROWS;
            const int sA0 = vrA - bA * SROWS, sB0 = vrB - bB * SROWS;
            const int sA = sA0 + (sA0 >= cc.row0 ? BQ : 0);
            const int sB = sB0 + (sB0 >= cc.row0 ? BQ : 0);
            const size_t rbA = (((size_t)bA * SEQ + sA) * HQ * HD) >> 2;
            const size_t rbB = (((size_t)bB * SEQ + sB) * HQ * HD) >> 2;
            float4 tmp[8];
            #pragma unroll
            for (int u = 0; u < 4; u++) tmp[u]     = __ldcs(cc.src_o + rbA + t + u * 256);
            #pragma unroll
            for (int u = 0; u < 4; u++) tmp[4 + u] = __ldcs(cc.src_o + rbB + t + u * 256);
            #pragma unroll
            for (int u = 0; u < 4; u++) __stcs(cc.dst_o + rbA + t + u * 256, tmp[u]);
            #pragma unroll
            for (int u = 0; u < 4; u++) __stcs(cc.dst_o + rbB + t + u * 256, tmp[4 + u]);
        }
    } else {
        const int hb = c - cc.nChunkO;
        const size_t base = (size_t)hb * SEQ;
        const int npos4 = SROWS >> 2;   // 992
        for (int p4 = t; p4 < npos4; p4 += 256) {
            const int p = p4 * 4;
            const int s = p + (p >= cc.row0 ? BQ : 0);
            __stcs(cc.dst_l + ((base + s) >> 2), __ldcs(cc.src_l + ((base + s) >> 2)));
        }
    }
}

__global__ __launch_bounds__(256, 2)
void oswa_fused_kernel(
    const float* __restrict__ q,   const float* __restrict__ k,
    const float* __restrict__ v,   const float* __restrict__ go,
    const float* __restrict__ glse,
    const float* __restrict__ gq,  const float* __restrict__ gk,
    const int* __restrict__ biq,   const int* __restrict__ bikv,
    float* __restrict__ out,
    int B, int nComputeBlocks, int nChunkO, int nChunkTotal, unsigned int qK)
{
    extern __shared__ uint32_t smw[];
    float* smf = (float*)smw;
    __shared__ int s_chunk;

    const int t    = threadIdx.x;
    const int lane = t & 31;
    const int w    = t >> 5;

    const int bidq  = biq[0];
    const int bidkv = bikv[0];
    const int row0  = bidq * BQ;
    const size_t O_ELEMS = (size_t)B * SEQ * HQ * HD;

    CopyCtx cc;
    cc.src_o = (const float4*)go;
    cc.dst_o = (float4*)out;
    cc.src_l = (const float4*)glse;
    cc.dst_l = (float4*)(out + O_ELEMS);
    cc.row0  = row0;
    cc.nChunkO = nChunkO;

    const int bid = blockIdx.x;
    bool terminated = false;   // this CTA has consumed its terminal queue slot

    if (bid < nComputeBlocks) {
        if (bid >= 148) {
            // stagger: second co-resident CTA copies N_PRE chunks first so DRAM
            // stays fed while its partner CTA runs the attention compute.
            for (int it = 0; it < N_PRE && !terminated; it++) {
                if (t == 0) s_chunk = (int)(atomicAdd(&g_chunk_counter, 1u) % qK);
                __syncthreads();
                const int c = s_chunk;
                __syncthreads();
                if (c < nChunkTotal) copy_chunk(cc, c, t);
                else terminated = true;
            }
        }

        // ---------------- attention tile: (batch, head, q-half of 64 rows) ----------------
        const int half  = bid & 1;
        const int h     = (bid >> 1) % HQ;
        const int batch = bid / (2 * HQ);
        const int kh    = h / (HQ / HKV);

        const int r4 = lane & 3;      // row-offset within 4-row group (loaders)
        const int qd = lane >> 2;     // d-group (loaders)

        // ---- K: load + RMSNorm + pack -> Ks2[kpair][j]  (4 rows/warp/iter, 4 iters) ----
        {
            #pragma unroll
            for (int it = 0; it < 4; it++) {
                const int j = it * 32 + w * 4 + r4;
                const float* kr = k + (((size_t)batch * BKV + j) * HKV + kh) * HD;
                float2 xv[8];
                float ss = 0.0f;
                #pragma unroll
                for (int p = 0; p < 8; p++) {
                    xv[p] = *(const float2*)(kr + 2 * qd + 16 * p);
                    ss += xv[p].x * xv[p].x + xv[p].y * xv[p].y;
                }
                ss += __shfl_xor_sync(0xffffffffu, ss, 4);
                ss += __shfl_xor_sync(0xffffffffu, ss, 8);
                ss += __shfl_xor_sync(0xffffffffu, ss, 16);
                const float rstd = rsqrtf(ss * (1.0f / HD) + EPSV);
                #pragma unroll
                for (int p = 0; p < 8; p++) {
                    const float2 g2 = *(const float2*)(gk + kh * HD + 2 * qd + 16 * p);
                    const int kp = qd + 8 * p;
                    smw[KS2_OFF + kv_idx(kp, j)] =
                        pack_bf16x2(xv[p].x * rstd * g2.x, xv[p].y * rstd * g2.y);
                }
            }
        }
        // ---- Q: load + RMSNorm + pack -> Qs2[kpair][i]  (2 iters) ----
        {
            #pragma unroll
            for (int it = 0; it < 2; it++) {
                const int i = it * 32 + w * 4 + r4;
                const int qrow = half * 64 + i;
                const float* qr = q + (((size_t)batch * BQ + qrow) * HQ + h) * HD;
                float2 xv[8];
                float ss = 0.0f;
                #pragma unroll
                for (int p = 0; p < 8; p++) {
                    xv[p] = *(const float2*)(qr + 2 * qd + 16 * p);
                    ss += xv[p].x * xv[p].x + xv[p].y * xv[p].y;
                }
                ss += __shfl_xor_sync(0xffffffffu, ss, 4);
                ss += __shfl_xor_sync(0xffffffffu, ss, 8);
                ss += __shfl_xor_sync(0xffffffffu, ss, 16);
                const float rstd = rsqrtf(ss * (1.0f / HD) + EPSV);
                #pragma unroll
                for (int p = 0; p < 8; p++) {
                    const float2 g2 = *(const float2*)(gq + h * HD + 2 * qd + 16 * p);
                    const int kp = qd + 8 * p;
                    smw[QS2_OFF + qp_idx(kp, i)] =
                        pack_bf16x2(xv[p].x * rstd * g2.x, xv[p].y * rstd * g2.y);
                }
            }
        }
        // ---- V: load + pack pairs along j -> Vs2[jpair][d]  (2 iters) ----
        {
            #pragma unroll
            for (int it = 0; it < 2; it++) {
                const int jp = it * 32 + w * 4 + r4;
                const float* v0 = v + (((size_t)batch * BKV + 2 * jp) * HKV + kh) * HD;
                const float* v1 = v0 + (size_t)HKV * HD;
                #pragma unroll
                for (int p = 0; p < 8; p++) {
                    const int d0 = 2 * qd + 16 * p;
                    const float2 f0 = *(const float2*)(v0 + d0);
                    const float2 f1 = *(const float2*)(v1 + d0);
                    const int idx = VS2_OFF + kv_idx(jp, d0);   // d0 even -> idx,idx+1 contiguous
                    uint2 wv;
                    wv.x = pack_bf16x2(f0.x, f1.x);
                    wv.y = pack_bf16x2(f0.y, f1.y);
                    *(uint2*)(smw + idx) = wv;
                }
            }
        }
        __syncthreads();

        // ---- GEMM1: S[64][128] = Qn * Kn^T via mma.m16n8k16 ----
        const int g   = lane >> 2;     // 0..7
        const int tg  = lane & 3;      // 0..3
        const int wm  = w & 3;
        const int wn  = w >> 2;
        const int m0  = wm * 16;
        const int nbase = wn * 64;

        float acc[8][4];
        #pragma unroll
        for (int nb = 0; nb < 8; nb++)
            #pragma unroll
            for (int c = 0; c < 4; c++) acc[nb][c] = 0.0f;

        #pragma unroll
        for (int ks = 0; ks < 8; ks++) {
            const int kb = ks * 8;
            const uint32_t a0 = smw[QS2_OFF + qp_idx(kb + tg,     m0 + g)];
            const uint32_t a1 = smw[QS2_OFF + qp_idx(kb + tg,     m0 + g + 8)];
            const uint32_t a2 = smw[QS2_OFF + qp_idx(kb + tg + 4, m0 + g)];
            const uint32_t a3 = smw[QS2_OFF + qp_idx(kb + tg + 4, m0 + g + 8)];
            #pragma unroll
            for (int nb = 0; nb < 8; nb++) {
                const uint32_t b0 = smw[KS2_OFF + kv_idx(kb + tg,     nbase + nb * 8 + g)];
                const uint32_t b1 = smw[KS2_OFF + kv_idx(kb + tg + 4, nbase + nb * 8 + g)];
                mma16816(acc[nb], a0, a1, a2, a3, b0, b1);
            }
        }

        // ---- cap + mask in-frag ----
        const int mA = m0 + g, mB = m0 + g + 8;
        const int qiA = row0 + half * 64 + mA;
        const int qiB = row0 + half * 64 + mB;
        #pragma unroll
        for (int nb = 0; nb < 8; nb++) {
            #pragma unroll
            for (int c = 0; c < 4; c++) {
                const int n_ = nbase + nb * 8 + 2 * tg + (c & 1);
                const int kj = bidkv * BKV + n_;
                const int qi = (c < 2) ? qiA : qiB;
                const float lg = CAPV * tanhf(acc[nb][c] * (SCL / CAPV));
                const bool allowed = (kj <= qi) && (kj >= qi - WIN) && (qi < SEQ) && (kj < SEQ);
                acc[nb][c] = allowed ? lg : -INFINITY;
            }
        }

        // ---- softmax: per-row max (tg-shfl + 2-warp smem combine) ----
        float pmA = -INFINITY, pmB = -INFINITY;
        #pragma unroll
        for (int nb = 0; nb < 8; nb++) {
            pmA = fmaxf(pmA, fmaxf(acc[nb][0], acc[nb][1]));
            pmB = fmaxf(pmB, fmaxf(acc[nb][2], acc[nb][3]));
        }
        pmA = fmaxf(pmA, __shfl_xor_sync(0xffffffffu, pmA, 1));
        pmA = fmaxf(pmA, __shfl_xor_sync(0xffffffffu, pmA, 2));
        pmB = fmaxf(pmB, __shfl_xor_sync(0xffffffffu, pmB, 1));
        pmB = fmaxf(pmB, __shfl_xor_sync(0xffffffffu, pmB, 2));
        if (tg == 0) {
            smf[PARTM_OFF + wn * 64 + mA] = pmA;
            smf[PARTM_OFF + wn * 64 + mB] = pmB;
        }
        __syncthreads();
        const float rowMA = fmaxf(smf[PARTM_OFF + mA], smf[PARTM_OFF + 64 + mA]);
        const float rowMB = fmaxf(smf[PARTM_OFF + mB], smf[PARTM_OFF + 64 + mB]);

        // ---- e = exp(x - rowmax), partial sums, write P (bf16x2) into Ps2 ----
        float psA = 0.0f, psB = 0.0f;
        #pragma unroll
        for (int nb = 0; nb < 8; nb++) {
            float e0 = (rowMA == -INFINITY) ? 0.0f : expf(acc[nb][0] - rowMA);
            float e1 = (rowMA == -INFINITY) ? 0.0f : expf(acc[nb][1] - rowMA);
            float e2 = (rowMB == -INFINITY) ? 0.0f : expf(acc[nb][2] - rowMB);
            float e3 = (rowMB == -INFINITY) ? 0.0f : expf(acc[nb][3] - rowMB);
            psA += e0 + e1;
            psB += e2 + e3;
            const int kp = (nbase >> 1) + nb * 4 + tg;
            smw[PS2_OFF + qp_idx(kp, mA)] = pack_bf16x2(e0, e1);
            smw[PS2_OFF + qp_idx(kp, mB)] = pack_bf16x2(e2, e3);
        }
        psA += __shfl_xor_sync(0xffffffffu, psA, 1);
        psA += __shfl_xor_sync(0xffffffffu, psA, 2);
        psB += __shfl_xor_sync(0xffffffffu, psB, 1);
        psB += __shfl_xor_sync(0xffffffffu, psB, 2);
        if (tg == 0) {
            smf[PARTS_OFF + wn * 64 + mA] = psA;
            smf[PARTS_OFF + wn * 64 + mB] = psB;
        }
        __syncthreads();

        // ---- per-row merge scalars (one thread per row) ----
        if (tg == 0 && wn == 0) {
            #pragma unroll
            for (int rsel = 0; rsel < 2; rsel++) {
                const int m_  = rsel ? mB : mA;
                const float rowM = rsel ? rowMB : rowMA;
                const float ssum = smf[PARTS_OFF + m_] + smf[PARTS_OFF + 64 + m_];
                const float lb = (ssum > 0.0f) ? (rowM + logf(ssum)) : -INFINITY;
                const int s = row0 + half * 64 + m_;
                const float lse_old = glse[((size_t)batch * HQ + h) * SEQ + s];
                const float mx = fmaxf(lse_old, lb);
                const float lse_new = (mx == -INFINITY) ? -INFINITY
                                     : mx + log1pf(expf(fminf(lse_old, lb) - mx));
                const bool fin = isfinite(lse_new);
                smf[SOLD_OFF + m_] = fin ? expf(lse_old - lse_new) : 0.0f;
                smf[SCB_OFF  + m_] = fin ? expf(rowM - lse_new)    : 0.0f;  // absorbs 1/sum
                out[O_ELEMS + ((size_t)batch * HQ + h) * SEQ + s] = lse_new;
            }
        }
        __syncthreads();

        // ---- GEMM2: O[64][128] = P * V via mma.m16n8k16 ----
        float oacc[8][4];
        #pragma unroll
        for (int nb = 0; nb < 8; nb++)
            #pragma unroll
            for (int c = 0; c < 4; c++) oacc[nb][c] = 0.0f;

        #pragma unroll
        for (int ks = 0; ks < 8; ks++) {
            const int kb = ks * 8;
            const uint32_t a0 = smw[PS2_OFF + qp_idx(kb + tg,     m0 + g)];
            const uint32_t a1 = smw[PS2_OFF + qp_idx(kb + tg,     m0 + g + 8)];
            const uint32_t a2 = smw[PS2_OFF + qp_idx(kb + tg + 4, m0 + g)];
            const uint32_t a3 = smw[PS2_OFF + qp_idx(kb + tg + 4, m0 + g + 8)];
            #pragma unroll
            for (int nb = 0; nb < 8; nb++) {
                const uint32_t b0 = smw[VS2_OFF + kv_idx(kb + tg,     nbase + nb * 8 + g)];
                const uint32_t b1 = smw[VS2_OFF + kv_idx(kb + tg + 4, nbase + nb * 8 + g)];
                mma16816(oacc[nb], a0, a1, a2, a3, b0, b1);
            }
        }

        // ---- online merge + writeout (float2 per row-pair fragment) ----
        const float coldA = smf[SOLD_OFF + mA], cbA = smf[SCB_OFF + mA];
        const float coldB = smf[SOLD_OFF + mB], cbB = smf[SCB_OFF + mB];
        const int sA_ = row0 + half * 64 + mA;
        const int sB_ = row0 + half * 64 + mB;
        const size_t baseA = (((size_t)batch * SEQ + sA_) * HQ + h) * HD;
        const size_t baseB = (((size_t)batch * SEQ + sB_) * HQ + h) * HD;
        #pragma unroll
        for (int nb = 0; nb < 8; nb++) {
            const int d0 = nbase + nb * 8 + 2 * tg;
            const float2 ooA = *(const float2*)(go + baseA + d0);
            const float2 ooB = *(const float2*)(go + baseB + d0);
            float2 wA, wB;
            wA.x = coldA * ooA.x + cbA * oacc[nb][0];
            wA.y = coldA * ooA.y + cbA * oacc[nb][1];
            wB.x = coldB * ooB.x + cbB * oacc[nb][2];
            wB.y = coldB * ooB.y + cbB * oacc[nb][3];
            *(float2*)(out + baseA + d0) = wA;
            *(float2*)(out + baseB + d0) = wB;
        }
    }

    // ---------------- dynamic copy of the remaining output regions ----------------
    while (!terminated) {
        if (t == 0) s_chunk = (int)(atomicAdd(&g_chunk_counter, 1u) % qK);
        __syncthreads();
        const int c = s_chunk;
        __syncthreads();
        if (c >= nChunkTotal) break;
        copy_chunk(cc, c, t);
    }
}

extern "C" void kernel_launch(void* const* d_in, const int* in_sizes, int n_in,
                              void* d_out, int out_size)
{
    const float* q    = (const float*)d_in[0];
    const float* k    = (const float*)d_in[1];
    const float* v    = (const float*)d_in[2];
    const float* go   = (const float*)d_in[3];
    const float* glse = (const float*)d_in[4];
    const float* gq   = (const float*)d_in[5];
    const float* gk   = (const float*)d_in[6];
    const int*   biq  = (const int*)d_in[7];
    const int*   bikv = (const int*)d_in[8];
    float* out = (float*)d_out;

    const int B = in_sizes[0] / (BQ * HQ * HD);                 // 4
    const int nCompute    = B * HQ * 2;                         // 256
    const int nChunkO     = (B * (SEQ - BQ)) / ROWS_PER_CHUNK;  // 1984
    const int nChunkTotal = nChunkO + B * HQ;                   // +128 lse chunks

    const size_t smem = SMEM_WORDS * sizeof(uint32_t);          // ~83.5 KB
    cudaFuncSetAttribute(oswa_fused_kernel,
                         cudaFuncAttributeMaxDynamicSharedMemorySize, (int)smem);

    const int grid = nCompute + 40;   // 296 = 2 CTAs/SM * 148 SMs
    const unsigned int qK = (unsigned int)(nChunkTotal + grid);  // atomics per launch

    oswa_fused_kernel<<<grid, 256, smem>>>(q, k, v, go, glse, gq, gk, biq, bikv,
                                           out, B, nCompute, nChunkO, nChunkTotal, qK);
}